// round 1
// baseline (speedup 1.0000x reference)
#include <cuda_runtime.h>

// Shapes are fixed by the problem: N=1024 nodes, D=256 node feat, H=256 hidden.
#define NN 1024
#define DD 256
#define HH 256

// Scratch (allocation-free rule: __device__ globals)
__device__ float g_p[DD];    // w1[:D]  @ w2
__device__ float g_q[DD];    // w1[D:]  @ w2
__device__ float g_c;        // b1 @ w2 + b2
__device__ float g_eu[NN];   // exp(-(u_i + c))
__device__ float g_ev[NN];   // exp(-v_i)

__device__ __forceinline__ float warp_reduce(float v) {
#pragma unroll
    for (int o = 16; o > 0; o >>= 1) v += __shfl_xor_sync(0xffffffffu, v, o);
    return v;
}

__device__ __forceinline__ float frcp(float x) {
    float y;
    asm("rcp.approx.f32 %0, %1;" : "=f"(y) : "f"(x));
    return y;
}

// Stage A: p = w1_top @ w2, q = w1_bot @ w2, c = b1.w2 + b2.  One warp per row.
__global__ void k_pq(const float* __restrict__ w1, const float* __restrict__ b1,
                     const float* __restrict__ w2, const float* __restrict__ b2) {
    int warp = (blockIdx.x * blockDim.x + threadIdx.x) >> 5;
    int lane = threadIdx.x & 31;
    if (warp < 2 * DD) {
        const float* row = w1 + (size_t)warp * HH;
        float acc = 0.f;
#pragma unroll
        for (int k = 0; k < HH / 32; k++) {
            int idx = lane + 32 * k;
            acc = fmaf(row[idx], w2[idx], acc);
        }
        acc = warp_reduce(acc);
        if (lane == 0) {
            if (warp < DD) g_p[warp] = acc;
            else           g_q[warp - DD] = acc;
        }
    } else if (warp == 2 * DD) {
        float acc = 0.f;
#pragma unroll
        for (int k = 0; k < HH / 32; k++) {
            int idx = lane + 32 * k;
            acc = fmaf(b1[idx], w2[idx], acc);
        }
        acc = warp_reduce(acc);
        if (lane == 0) g_c = acc + b2[0];
    }
}

// Stage B: u_i = z_i.p, v_i = z_i.q, then eu_i = exp(-(u_i+c)), ev_i = exp(-v_i).
// One warp per node row.
__global__ void k_uv(const float* __restrict__ z) {
    int warp = (blockIdx.x * blockDim.x + threadIdx.x) >> 5;
    int lane = threadIdx.x & 31;
    const float* row = z + (size_t)warp * DD;
    float su = 0.f, sv = 0.f;
#pragma unroll
    for (int k = 0; k < DD / 32; k++) {
        int idx = lane + 32 * k;
        float zv = row[idx];
        su = fmaf(zv, g_p[idx], su);
        sv = fmaf(zv, g_q[idx], sv);
    }
    su = warp_reduce(su);
    sv = warp_reduce(sv);
    if (lane == 0) {
        g_eu[warp] = __expf(-(su + g_c));
        g_ev[warp] = __expf(-sv);
    }
}

// Stage C: adj[i,j] = 0.5*(1/(1+eu_i*ev_j) + 1/(1+eu_j*ev_i)).
// One block per row i, float4 stores (4 cols/thread).
__global__ void k_adj(float* __restrict__ out) {
    int i = blockIdx.x;
    int t = threadIdx.x;
    int j = t * 4;
    float eui = g_eu[i];
    float evi = g_ev[i];
    float4 euj = *reinterpret_cast<const float4*>(g_eu + j);
    float4 evj = *reinterpret_cast<const float4*>(g_ev + j);
    float4 o;
    o.x = 0.5f * (frcp(fmaf(eui, evj.x, 1.f)) + frcp(fmaf(euj.x, evi, 1.f)));
    o.y = 0.5f * (frcp(fmaf(eui, evj.y, 1.f)) + frcp(fmaf(euj.y, evi, 1.f)));
    o.z = 0.5f * (frcp(fmaf(eui, evj.z, 1.f)) + frcp(fmaf(euj.z, evi, 1.f)));
    o.w = 0.5f * (frcp(fmaf(eui, evj.w, 1.f)) + frcp(fmaf(euj.w, evi, 1.f)));
    reinterpret_cast<float4*>(out)[(size_t)i * (NN / 4) + t] = o;
}

extern "C" void kernel_launch(void* const* d_in, const int* in_sizes, int n_in,
                              void* d_out, int out_size) {
    const float* z  = (const float*)d_in[0];  // [N, D]
    const float* w1 = (const float*)d_in[1];  // [2D, H]
    const float* b1 = (const float*)d_in[2];  // [H]
    const float* w2 = (const float*)d_in[3];  // [H]
    const float* b2 = (const float*)d_in[4];  // [1]
    float* out = (float*)d_out;               // [N, N]

    // 512 row-warps + 1 warp for c  -> 65 blocks of 8 warps
    k_pq<<<65, 256>>>(w1, b1, w2, b2);
    // 1024 row-warps -> 128 blocks of 8 warps
    k_uv<<<NN / 8, 256>>>(z);
    // one block per output row
    k_adj<<<NN, 256>>>(out);
}

// round 2
// speedup vs baseline: 1.0209x; 1.0209x over previous
#include <cuda_runtime.h>

// Shapes fixed by problem: N=1024 nodes, D=256 feat, H=256 hidden.
#define NN 1024
#define DD 256
#define HH 256
#define NBLK 128          // <= 148 SMs -> all CTAs resident -> device barrier is safe
#define NTHR 256

// Scratch (__device__ globals: allocation-free rule)
__device__ float g_p[DD];     // w1[:D] @ w2
__device__ float g_q[DD];     // w1[D:] @ w2
__device__ float g_c;         // b1.w2 + b2
__device__ float g_eu[NN];    // exp(-(u_i + c))
__device__ float g_ev[NN];    // exp(-v_i)

__device__ unsigned g_bar_count = 0;   // resets to 0 each barrier crossing
__device__ unsigned g_bar_gen   = 0;   // monotonically increments (wrap-safe)

__device__ __forceinline__ float warp_reduce(float v) {
#pragma unroll
    for (int o = 16; o > 0; o >>= 1) v += __shfl_xor_sync(0xffffffffu, v, o);
    return v;
}

__device__ __forceinline__ float frcp(float x) {
    float y;
    asm("rcp.approx.f32 %0, %1;" : "=f"(y) : "f"(x));
    return y;
}

// Sense-reversing grid barrier. Safe because all NBLK CTAs are co-resident.
__device__ __forceinline__ void grid_barrier() {
    __syncthreads();
    if (threadIdx.x == 0) {
        __threadfence();  // make this block's global writes visible
        unsigned gen = *(volatile unsigned*)&g_bar_gen;
        unsigned t = atomicAdd(&g_bar_count, 1u);
        if (t == NBLK - 1) {
            g_bar_count = 0;
            __threadfence();
            atomicAdd(&g_bar_gen, 1u);   // release
        } else {
            while (*(volatile unsigned*)&g_bar_gen == gen) { }
        }
        __threadfence();  // acquire other blocks' writes
    }
    __syncthreads();
}

__global__ void __launch_bounds__(NTHR, 1)
fused_decoder(const float* __restrict__ z,  const float* __restrict__ w1,
              const float* __restrict__ b1, const float* __restrict__ w2,
              const float* __restrict__ b2, float* __restrict__ out) {
    const int lane  = threadIdx.x & 31;
    const int wid   = threadIdx.x >> 5;                       // 0..7
    const int gwarp = blockIdx.x * (NTHR / 32) + wid;         // 0..1023

    // ---- Phase A: p = w1_top@w2, q = w1_bot@w2, c = b1.w2 + b2 ----
    if (gwarp < 2 * DD) {
        const float* row = w1 + (size_t)gwarp * HH;
        float acc = 0.f;
#pragma unroll
        for (int k = 0; k < HH / 32; k++) {
            int idx = lane + 32 * k;
            acc = fmaf(row[idx], w2[idx], acc);
        }
        acc = warp_reduce(acc);
        if (lane == 0) {
            if (gwarp < DD) g_p[gwarp] = acc;
            else            g_q[gwarp - DD] = acc;
        }
    } else if (gwarp == 2 * DD) {
        float acc = 0.f;
#pragma unroll
        for (int k = 0; k < HH / 32; k++) {
            int idx = lane + 32 * k;
            acc = fmaf(b1[idx], w2[idx], acc);
        }
        acc = warp_reduce(acc);
        if (lane == 0) g_c = acc + b2[0];
    }

    grid_barrier();

    // ---- Phase B: eu_i = exp(-(z_i.p + c)), ev_i = exp(-(z_i.q)) ----
    {
        const float* row = z + (size_t)gwarp * DD;
        float su = 0.f, sv = 0.f;
#pragma unroll
        for (int k = 0; k < DD / 32; k++) {
            int idx = lane + 32 * k;
            float zv = row[idx];
            su = fmaf(zv, g_p[idx], su);
            sv = fmaf(zv, g_q[idx], sv);
        }
        su = warp_reduce(su);
        sv = warp_reduce(sv);
        if (lane == 0) {
            g_eu[gwarp] = __expf(-(su + g_c));
            g_ev[gwarp] = __expf(-sv);
        }
    }

    grid_barrier();

    // ---- Phase C: adj[i,j] = 0.5*(sig(u_i+v_j+c) + sig(u_j+v_i+c))
    //             = 0.5*(1/(1+eu_i*ev_j) + 1/(1+eu_j*ev_i)) ----
    const int t = threadIdx.x;                  // 256 threads x float4 = 1024 cols
    const int j = t * 4;
    const float4 euj = *reinterpret_cast<const float4*>(g_eu + j);
    const float4 evj = *reinterpret_cast<const float4*>(g_ev + j);
#pragma unroll
    for (int r = 0; r < NN / NBLK; r++) {
        const int i = blockIdx.x * (NN / NBLK) + r;
        const float eui = g_eu[i];
        const float evi = g_ev[i];
        float4 o;
        o.x = 0.5f * (frcp(fmaf(eui, evj.x, 1.f)) + frcp(fmaf(euj.x, evi, 1.f)));
        o.y = 0.5f * (frcp(fmaf(eui, evj.y, 1.f)) + frcp(fmaf(euj.y, evi, 1.f)));
        o.z = 0.5f * (frcp(fmaf(eui, evj.z, 1.f)) + frcp(fmaf(euj.z, evi, 1.f)));
        o.w = 0.5f * (frcp(fmaf(eui, evj.w, 1.f)) + frcp(fmaf(euj.w, evi, 1.f)));
        reinterpret_cast<float4*>(out)[(size_t)i * (NN / 4) + t] = o;
    }
}

extern "C" void kernel_launch(void* const* d_in, const int* in_sizes, int n_in,
                              void* d_out, int out_size) {
    const float* z  = (const float*)d_in[0];  // [N, D]
    const float* w1 = (const float*)d_in[1];  // [2D, H]
    const float* b1 = (const float*)d_in[2];  // [H]
    const float* w2 = (const float*)d_in[3];  // [H]
    const float* b2 = (const float*)d_in[4];  // [1]
    float* out = (float*)d_out;               // [N, N]

    fused_decoder<<<NBLK, NTHR>>>(z, w1, b1, w2, b2, out);
}